// round 4
// baseline (speedup 1.0000x reference)
#include <cuda_runtime.h>
#include <math.h>

// Problem constants
#define Bb 4
#define Nn 8192
#define Cc 512
#define Hh 8
#define Dd 64
#define SPL 4                          // split-K for G = x^T ctx over N
#define OUT_ELEMS (Bb*Nn*Cc)           // 16777216
#define ATT_ELEMS (Bb*Hh*Dd*Dd)        // 131072

// Static scratch (~92 MB; allocations forbidden -> __device__ globals)
__device__ float g_Gpart[SPL*Bb*Cc*Cc];   // 16 MB  split-K partials of G
__device__ float g_G[Bb*Cc*Cc];           // 4 MB   G[b] stored transposed: [c2][c1]
__device__ float g_T[Bb*Cc*Cc];           // 4 MB   T[b] = Wq @ G[b]
__device__ float g_V[Bb*Nn*Cc];           // 64 MB  V projection
__device__ float g_att[ATT_ELEMS];        // 0.5 MB softmaxed attention
__device__ float g_M[Bb*Cc*Cc];           // 4 MB   fused proj*att weights
__device__ float g_sx[Bb][Cc];            // column sums of x
__device__ float g_sc[Bb][Cc];            // column sums of ctx

#define SROW 132

// ---------------------------------------------------------------------------
// SGEMM: Cout = A @ W^T (+ bias). A [M x K], W [N x K] row-major.
// 128x128 tile, BK=8, 256 threads, 8x8/thread, double-buffered smem.
// ---------------------------------------------------------------------------
__device__ __forceinline__ void sgemm128(
    const float* __restrict__ A, const float* __restrict__ W,
    const float* __restrict__ bias, float* __restrict__ Cout,
    const int K, const int N)
{
    __shared__ float As[2][8][SROW];
    __shared__ float Bs[2][8][SROW];

    const int tid = threadIdx.x;
    const int bm  = blockIdx.x, bn = blockIdx.y;
    const int tr4 = ((tid >> 4) & 15) << 2;
    const int tc4 = (tid & 15) << 2;
    const int lrow = tid >> 1;
    const int lc4  = (tid & 1) << 2;

    const float* Ap = A + (size_t)(bm*128 + lrow) * K + lc4;
    const float* Wp = W + (size_t)(bn*128 + lrow) * K + lc4;

    float acc[8][8];
    #pragma unroll
    for (int i = 0; i < 8; ++i)
        #pragma unroll
        for (int j = 0; j < 8; ++j) acc[i][j] = 0.f;

    {
        float4 av = *(const float4*)Ap;
        float4 wv = *(const float4*)Wp;
        As[0][lc4+0][lrow] = av.x; As[0][lc4+1][lrow] = av.y;
        As[0][lc4+2][lrow] = av.z; As[0][lc4+3][lrow] = av.w;
        Bs[0][lc4+0][lrow] = wv.x; Bs[0][lc4+1][lrow] = wv.y;
        Bs[0][lc4+2][lrow] = wv.z; Bs[0][lc4+3][lrow] = wv.w;
    }
    __syncthreads();

    int buf = 0;
    for (int k0 = 0; k0 < K; k0 += 8) {
        float4 av, wv;
        const bool has = (k0 + 8) < K;
        if (has) {
            av = *(const float4*)(Ap + k0 + 8);
            wv = *(const float4*)(Wp + k0 + 8);
        }
        #pragma unroll
        for (int kk = 0; kk < 8; ++kk) {
            float rA[8], rB[8];
            *(float4*)&rA[0] = *(const float4*)&As[buf][kk][tr4];
            *(float4*)&rA[4] = *(const float4*)&As[buf][kk][tr4 + 64];
            *(float4*)&rB[0] = *(const float4*)&Bs[buf][kk][tc4];
            *(float4*)&rB[4] = *(const float4*)&Bs[buf][kk][tc4 + 64];
            #pragma unroll
            for (int i = 0; i < 8; ++i)
                #pragma unroll
                for (int j = 0; j < 8; ++j)
                    acc[i][j] = fmaf(rA[i], rB[j], acc[i][j]);
        }
        if (has) {
            const int nb = buf ^ 1;
            As[nb][lc4+0][lrow] = av.x; As[nb][lc4+1][lrow] = av.y;
            As[nb][lc4+2][lrow] = av.z; As[nb][lc4+3][lrow] = av.w;
            Bs[nb][lc4+0][lrow] = wv.x; Bs[nb][lc4+1][lrow] = wv.y;
            Bs[nb][lc4+2][lrow] = wv.z; Bs[nb][lc4+3][lrow] = wv.w;
        }
        __syncthreads();
        buf ^= 1;
    }

    float bv[8];
    #pragma unroll
    for (int hj = 0; hj < 2; ++hj)
        #pragma unroll
        for (int j = 0; j < 4; ++j)
            bv[hj*4+j] = bias ? bias[bn*128 + hj*64 + tc4 + j] : 0.f;

    #pragma unroll
    for (int hi = 0; hi < 2; ++hi)
        #pragma unroll
        for (int i = 0; i < 4; ++i) {
            const int r = bm*128 + hi*64 + tr4 + i;
            #pragma unroll
            for (int hj = 0; hj < 2; ++hj) {
                const int c = bn*128 + hj*64 + tc4;
                float4 v;
                v.x = acc[hi*4+i][hj*4+0] + bv[hj*4+0];
                v.y = acc[hi*4+i][hj*4+1] + bv[hj*4+1];
                v.z = acc[hi*4+i][hj*4+2] + bv[hj*4+2];
                v.w = acc[hi*4+i][hj*4+3] + bv[hj*4+3];
                *(float4*)&Cout[(size_t)r * N + c] = v;
            }
        }
}

// ---------------------------------------------------------------------------
// K1: column sums sx[b][c] = sum_n x[b,n,c], sc likewise for ctx.
// ---------------------------------------------------------------------------
__global__ void colsum_kernel(const float* __restrict__ x,
                              const float* __restrict__ ctx)
{
    const float* src = blockIdx.z ? ctx : x;
    float* dst = blockIdx.z ? &g_sc[0][0] : &g_sx[0][0];
    const int b = blockIdx.y;
    const int c = blockIdx.x*128 + (threadIdx.x & 127);
    const int q = threadIdx.x >> 7;            // 0..3
    const float* p = src + (size_t)b*Nn*Cc + (size_t)q*(Nn/4)*Cc + c;
    float s = 0.f;
    for (int n = 0; n < Nn/4; ++n) s += p[(size_t)n*Cc];
    __shared__ float sh[512];
    sh[threadIdx.x] = s;
    __syncthreads();
    if (q == 0)
        dst[b*Cc + c] = sh[threadIdx.x] + sh[threadIdx.x+128]
                      + sh[threadIdx.x+256] + sh[threadIdx.x+384];
}

// ---------------------------------------------------------------------------
// K2: G partials. Gt[b][c2][c1] = sum_n ctx[b,n,c2] * x[b,n,c1]   ("TN" GEMM)
// ---------------------------------------------------------------------------
__global__ __launch_bounds__(256, 2)
void spart_kernel(const float* __restrict__ x, const float* __restrict__ ctx)
{
    const int t = blockIdx.x;
    const int b = blockIdx.y;
    const int s = blockIdx.z;
    const int c2t = (t >> 2) * 128, c1t = (t & 3) * 128;
    const float* Cp = ctx + (size_t)b*Nn*Cc + c2t;
    const float* Xp = x   + (size_t)b*Nn*Cc + c1t;

    __shared__ float As[2][8][SROW];   // [k(n)][c2]
    __shared__ float Bs[2][8][SROW];   // [k(n)][c1]

    const int tid = threadIdx.x;
    const int lr  = tid >> 5;          // 0..7 (n within slab)
    const int lc4 = (tid & 31) << 2;   // 0..124
    const int tr4 = ((tid >> 4) & 15) << 2;
    const int tc4 = (tid & 15) << 2;

    float acc[8][8];
    #pragma unroll
    for (int i = 0; i < 8; ++i)
        #pragma unroll
        for (int j = 0; j < 8; ++j) acc[i][j] = 0.f;

    const int nbeg = s * (Nn / SPL);
    const int nend = nbeg + Nn / SPL;

    {
        float4 cv = *(const float4*)(Cp + (size_t)(nbeg+lr)*Cc + lc4);
        float4 xv = *(const float4*)(Xp + (size_t)(nbeg+lr)*Cc + lc4);
        *(float4*)&As[0][lr][lc4] = cv;
        *(float4*)&Bs[0][lr][lc4] = xv;
    }
    __syncthreads();

    int buf = 0;
    for (int n0 = nbeg; n0 < nend; n0 += 8) {
        float4 cv, xv;
        const bool has = (n0 + 8) < nend;
        if (has) {
            cv = *(const float4*)(Cp + (size_t)(n0+8+lr)*Cc + lc4);
            xv = *(const float4*)(Xp + (size_t)(n0+8+lr)*Cc + lc4);
        }
        #pragma unroll
        for (int kk = 0; kk < 8; ++kk) {
            float rA[8], rB[8];
            *(float4*)&rA[0] = *(const float4*)&As[buf][kk][tr4];
            *(float4*)&rA[4] = *(const float4*)&As[buf][kk][tr4 + 64];
            *(float4*)&rB[0] = *(const float4*)&Bs[buf][kk][tc4];
            *(float4*)&rB[4] = *(const float4*)&Bs[buf][kk][tc4 + 64];
            #pragma unroll
            for (int i = 0; i < 8; ++i)
                #pragma unroll
                for (int j = 0; j < 8; ++j)
                    acc[i][j] = fmaf(rA[i], rB[j], acc[i][j]);
        }
        if (has) {
            const int nb = buf ^ 1;
            *(float4*)&As[nb][lr][lc4] = cv;
            *(float4*)&Bs[nb][lr][lc4] = xv;
        }
        __syncthreads();
        buf ^= 1;
    }

    float* P = g_Gpart + ((size_t)s*Bb + b) * Cc * Cc;
    #pragma unroll
    for (int hi = 0; hi < 2; ++hi)
        #pragma unroll
        for (int i = 0; i < 4; ++i) {
            const int r = c2t + hi*64 + tr4 + i;
            #pragma unroll
            for (int hj = 0; hj < 2; ++hj) {
                const int c = c1t + hj*64 + tc4;
                float4 v;
                v.x = acc[hi*4+i][hj*4+0]; v.y = acc[hi*4+i][hj*4+1];
                v.z = acc[hi*4+i][hj*4+2]; v.w = acc[hi*4+i][hj*4+3];
                *(float4*)&P[(size_t)r * Cc + c] = v;
            }
        }
}

// K3: reduce split-K partials into g_G.
__global__ void sreduce_kernel()
{
    const size_t i4 = ((size_t)blockIdx.x * 256 + threadIdx.x) * 4;
    const size_t stride = (size_t)Bb * Cc * Cc;
    float4 a = *(const float4*)&g_Gpart[i4];
    #pragma unroll
    for (int s = 1; s < SPL; ++s) {
        float4 p = *(const float4*)&g_Gpart[s*stride + i4];
        a.x += p.x; a.y += p.y; a.z += p.z; a.w += p.w;
    }
    *(float4*)&g_G[i4] = a;
}

// K4: V projection.
__global__ __launch_bounds__(256, 2)
void vproj_kernel(const float* __restrict__ ctx, const float* __restrict__ Wv,
                  const float* __restrict__ bv)
{
    sgemm128(ctx, Wv, bv, g_V, Cc, Cc);
}

// K5: T[b] = Wq @ G[b]
__global__ __launch_bounds__(256, 2)
void T_kernel(const float* __restrict__ Wq)
{
    const int b = blockIdx.z;
    sgemm128(Wq, g_G + (size_t)b*Cc*Cc, nullptr, g_T + (size_t)b*Cc*Cc, Cc, Cc);
}

// ---------------------------------------------------------------------------
// K6: per (b,h): logits L = T[b][h64:,:] @ Wk[h64:,:]^T + rank-1 bias terms,
// scale, softmax over e; write g_att (+ att output). grid (Bb*Hh), 256 thr.
// ---------------------------------------------------------------------------
#define TSROW 68   // stride 68: float4-aligned (68%4==0), banks spread (68%32==4)

__global__ __launch_bounds__(256)
void att_kernel(const float* __restrict__ Wq, const float* __restrict__ bq_,
                const float* __restrict__ Wk, const float* __restrict__ bk_,
                float* __restrict__ att_out)
{
    const int bh = blockIdx.x;
    const int b = bh >> 3, h = bh & 7, h64 = h * 64;

    __shared__ float Ts[64][TSROW]; // [d][k]  (float4 stores -> stride mult of 4)
    __shared__ float Wks[64][65];   // [k][e]  (scalar transposed stores)
    __shared__ float u[64], w[64];

    const int tid = threadIdx.x;
    const int d = tid >> 2, g = tid & 3;

    // rank-1 vectors: u[d] = Wq_h[d,:]·sx[b],  w[e] = Wk_h[e,:]·sc[b]
    if (tid < 64) {
        const float* r = Wq + (size_t)(h64 + tid) * Cc;
        float a = 0.f;
        for (int c = 0; c < Cc; ++c) a = fmaf(r[c], g_sx[b][c], a);
        u[tid] = a;
    } else if (tid < 128) {
        const int e = tid - 64;
        const float* r = Wk + (size_t)(h64 + e) * Cc;
        float a = 0.f;
        for (int c = 0; c < Cc; ++c) a = fmaf(r[c], g_sc[b][c], a);
        w[e] = a;
    }

    float acc[16];
    #pragma unroll
    for (int j = 0; j < 16; ++j) acc[j] = 0.f;

    for (int k0 = 0; k0 < Cc; k0 += 64) {
        __syncthreads();
        for (int i = tid; i < 64*16; i += 256) {
            const int row = i >> 4, c4 = (i & 15) << 2;
            float4 tv = *(const float4*)&g_T[((size_t)b*Cc + h64 + row)*Cc + k0 + c4];
            *(float4*)&Ts[row][c4] = tv;
            float4 wv = *(const float4*)&Wk[(size_t)(h64 + row)*Cc + k0 + c4];
            Wks[c4+0][row] = wv.x; Wks[c4+1][row] = wv.y;
            Wks[c4+2][row] = wv.z; Wks[c4+3][row] = wv.w;
        }
        __syncthreads();
        #pragma unroll 16
        for (int k = 0; k < 64; ++k) {
            const float tv = Ts[d][k];
            #pragma unroll
            for (int j = 0; j < 16; ++j)
                acc[j] = fmaf(tv, Wks[k][g*16 + j], acc[j]);
        }
    }
    __syncthreads();

    // rank-1 terms + scale
    const float bqd = bq_[h64 + d];
    const float ud  = u[d];
    float v[16];
    #pragma unroll
    for (int j = 0; j < 16; ++j) {
        const int e = g*16 + j;
        const float l = acc[j] + bqd * w[e] + bk_[h64 + e] * ud
                      + (float)Nn * bqd * bk_[h64 + e];
        v[j] = l * 0.125f;   // 1/sqrt(64)
    }

    // softmax over e: 4 threads per row d
    float mx = v[0];
    #pragma unroll
    for (int j = 1; j < 16; ++j) mx = fmaxf(mx, v[j]);
    mx = fmaxf(mx, __shfl_xor_sync(0xffffffff, mx, 1));
    mx = fmaxf(mx, __shfl_xor_sync(0xffffffff, mx, 2));
    float sum = 0.f;
    #pragma unroll
    for (int j = 0; j < 16; ++j) { v[j] = expf(v[j] - mx); sum += v[j]; }
    sum += __shfl_xor_sync(0xffffffff, sum, 1);
    sum += __shfl_xor_sync(0xffffffff, sum, 2);
    const float inv = 1.f / sum;

    float4 o[4];
    #pragma unroll
    for (int q = 0; q < 4; ++q) {
        o[q].x = v[q*4+0]*inv; o[q].y = v[q*4+1]*inv;
        o[q].z = v[q*4+2]*inv; o[q].w = v[q*4+3]*inv;
    }
    const size_t base = ((size_t)bh*64 + d)*64 + g*16;
    #pragma unroll
    for (int q = 0; q < 4; ++q) {
        *(float4*)&g_att[base + q*4] = o[q];
        if (att_out) *(float4*)&att_out[base + q*4] = o[q];
    }
}

// ---------------------------------------------------------------------------
// K7: M[b][cp][h64+e] = sum_d proj_w[cp][h64+d] * att[b,h,d,e]
// ---------------------------------------------------------------------------
__global__ __launch_bounds__(256)
void buildM_kernel(const float* __restrict__ proj_w)
{
    const int b   = blockIdx.x;
    const int cp0 = blockIdx.y * 64;
    __shared__ float atts[64][65];
    const int tid = threadIdx.x;

    for (int h = 0; h < Hh; ++h) {
        for (int i = tid; i < 64*64; i += 256) {
            const int d2 = i >> 6, e = i & 63;
            atts[d2][e] = g_att[(((size_t)(b*Hh + h)*64) + d2)*64 + e];
        }
        __syncthreads();
        for (int ww = tid; ww < 64*16; ww += 256) {
            const int cp = cp0 + (ww >> 4);
            const int e4 = (ww & 15) << 2;
            const float* pw = proj_w + (size_t)cp*Cc + h*64;
            float a0=0.f, a1=0.f, a2=0.f, a3=0.f;
            #pragma unroll 16
            for (int d2 = 0; d2 < 64; ++d2) {
                const float p = pw[d2];
                a0 = fmaf(p, atts[d2][e4+0], a0);
                a1 = fmaf(p, atts[d2][e4+1], a1);
                a2 = fmaf(p, atts[d2][e4+2], a2);
                a3 = fmaf(p, atts[d2][e4+3], a3);
            }
            float4 vv; vv.x=a0; vv.y=a1; vv.z=a2; vv.w=a3;
            *(float4*)&g_M[(((size_t)b*Cc + cp)*Cc) + h*64 + e4] = vv;
        }
        __syncthreads();
    }
}

// K8: out[b] = V[b] @ M[b]^T + proj_b.
__global__ __launch_bounds__(256, 2)
void out_kernel(const float* __restrict__ proj_b, float* __restrict__ out)
{
    const int b = blockIdx.z;
    sgemm128(g_V + (size_t)b*Nn*Cc, g_M + (size_t)b*Cc*Cc,
             proj_b, out + (size_t)b*Nn*Cc, Cc, Cc);
}

extern "C" void kernel_launch(void* const* d_in, const int* in_sizes, int n_in,
                              void* d_out, int out_size)
{
    const float* x      = (const float*)d_in[0];
    const float* ctx    = (const float*)d_in[1];
    const float* Wq     = (const float*)d_in[2];
    const float* bq     = (const float*)d_in[3];
    const float* Wk     = (const float*)d_in[4];
    const float* bk     = (const float*)d_in[5];
    const float* Wv     = (const float*)d_in[6];
    const float* bv     = (const float*)d_in[7];
    const float* proj_w = (const float*)d_in[8];
    const float* proj_b = (const float*)d_in[9];
    float* out = (float*)d_out;

    float* att_out = (out_size >= OUT_ELEMS + ATT_ELEMS) ? (out + OUT_ELEMS) : nullptr;

    colsum_kernel<<<dim3(Cc/128, Bb, 2), 512>>>(x, ctx);
    spart_kernel <<<dim3(16, Bb, SPL), 256>>>(x, ctx);
    sreduce_kernel<<<1024, 256>>>();
    vproj_kernel <<<dim3(Bb*Nn/128, Cc/128), 256>>>(ctx, Wv, bv);
    T_kernel     <<<dim3(Cc/128, Cc/128, Bb), 256>>>(Wq);
    att_kernel   <<<Bb*Hh, 256>>>(Wq, bq, Wk, bk, att_out);
    buildM_kernel<<<dim3(Bb, Cc/64), 256>>>(proj_w);
    out_kernel   <<<dim3(Nn/128, Cc/128, Bb), 256>>>(proj_b, out);
}

// round 9
// speedup vs baseline: 1.2137x; 1.2137x over previous
#include <cuda_runtime.h>
#include <cuda_bf16.h>
#include <cstdint>
#include <math.h>

// Problem constants
#define Bb 4
#define Nn 8192
#define Cc 512
#define Hh 8
#define Dd 64
#define SPL 4                          // split-K for G over N
#define OUT_ELEMS (Bb*Nn*Cc)           // 16777216
#define ATT_ELEMS (Bb*Hh*Dd*Dd)       // 131072

// ---------------------------------------------------------------------------
// Static scratch
// ---------------------------------------------------------------------------
__device__ float g_Gpart[SPL*Bb*Cc*Cc];     // 16 MB  split-K partials of Gt
__device__ float g_T[Bb*Cc*Cc];             // 4 MB   T[b][d'][c2] fp32
__device__ float g_att[ATT_ELEMS];
__device__ float g_sx[Bb][Cc];
__device__ float g_sc[Bb][Cc];

__device__ __nv_bfloat16 g_ch[Bb*Nn*Cc],  g_cl[Bb*Nn*Cc];    // ctx (K=c major)
__device__ __nv_bfloat16 g_xTh[Bb*Cc*Nn], g_xTl[Bb*Cc*Nn];   // x^T  (K=n major)
__device__ __nv_bfloat16 g_cTh[Bb*Cc*Nn], g_cTl[Bb*Cc*Nn];   // ctx^T
__device__ __nv_bfloat16 g_Vh[Bb*Nn*Cc],  g_Vl[Bb*Nn*Cc];    // V projection
__device__ __nv_bfloat16 g_Gth[Bb*Cc*Cc], g_Gtl[Bb*Cc*Cc];   // Gt[c2][c1]
__device__ __nv_bfloat16 g_Mh[Bb*Cc*Cc],  g_Ml[Bb*Cc*Cc];    // fused M
__device__ __nv_bfloat16 g_Wvh[Cc*Cc], g_Wvl[Cc*Cc];
__device__ __nv_bfloat16 g_Wqh[Cc*Cc], g_Wql[Cc*Cc];

// ---------------------------------------------------------------------------
// mma.sync m16n8k16 bf16 (sm_80+; supported HMMA path on sm_100)
// ---------------------------------------------------------------------------
__device__ __forceinline__ void mma16816(float* c, const uint32_t* a, const uint32_t* b)
{
    asm volatile(
        "mma.sync.aligned.m16n8k16.row.col.f32.bf16.bf16.f32 "
        "{%0,%1,%2,%3}, {%4,%5,%6,%7}, {%8,%9}, {%0,%1,%2,%3};"
        : "+f"(c[0]), "+f"(c[1]), "+f"(c[2]), "+f"(c[3])
        : "r"(a[0]), "r"(a[1]), "r"(a[2]), "r"(a[3]), "r"(b[0]), "r"(b[1]));
}

// ---------------------------------------------------------------------------
// GEMM tile: D[128x128] = sum_k A[128,K] B[128,K]^T, split-3 bf16 hi/lo.
// 256 threads (8 warps, warp tile 32x64), Kc=32, SINGLE static smem buffer
// (40 KB, no dynamic smem / no cudaFuncSetAttribute). Register double-buffer:
// next chunk prefetched to regs while MMAs consume current smem chunk.
// Row stride 40 bf16 keeps frag loads conflict-free.
// ---------------------------------------------------------------------------
#define SK 40
#define TILE_ELEMS (128*SK)                 // 5120 bf16 per tile

__device__ void tc_gemm_tile(
    const __nv_bfloat16* __restrict__ Ah, const __nv_bfloat16* __restrict__ Al, int lda,
    const __nv_bfloat16* __restrict__ Bh, const __nv_bfloat16* __restrict__ Bl, int ldb,
    int K, int row0, int col0,
    const float* __restrict__ bias,
    float* __restrict__ outF,
    __nv_bfloat16* __restrict__ outH, __nv_bfloat16* __restrict__ outL,
    int ldo)
{
    __shared__ __nv_bfloat16 sm[4*TILE_ELEMS];   // 40960 B static

    const int tid  = threadIdx.x;
    const int lane = tid & 31;
    const int wid  = tid >> 5;
    const int wm   = wid >> 1;          // 0..3  (m block of 32)
    const int wn   = wid & 1;           // 0..1  (n block of 64)
    const int gr   = lane >> 2;         // 0..7
    const int kp   = (lane & 3) << 1;   // 0,2,4,6

    const __nv_bfloat16* srcs[4];
    srcs[0] = Ah + (size_t)row0 * lda;
    srcs[1] = Al + (size_t)row0 * lda;
    srcs[2] = Bh + (size_t)col0 * ldb;
    srcs[3] = Bl + (size_t)col0 * ldb;
    const int lds[4] = {lda, lda, ldb, ldb};

    const int prow = tid >> 1;                 // 0..127
    const int pc0  = (tid & 1) * 16;

    float acc[64];
    #pragma unroll
    for (int i = 0; i < 64; ++i) acc[i] = 0.f;

    // prefetch chunk 0 into registers
    uint2 pf[4][4];
    #pragma unroll
    for (int t = 0; t < 4; ++t)
        #pragma unroll
        for (int i = 0; i < 4; ++i)
            pf[t][i] = *(const uint2*)(srcs[t] + (size_t)prow*lds[t] + pc0 + i*4);

    const int nch = K / 32;
    for (int c = 0; c < nch; ++c) {
        __syncthreads();                // smem free (previous compute done)
        #pragma unroll
        for (int t = 0; t < 4; ++t)
            #pragma unroll
            for (int i = 0; i < 4; ++i)
                *(uint2*)(sm + t*TILE_ELEMS + prow*SK + pc0 + i*4) = pf[t][i];
        __syncthreads();

        if (c + 1 < nch) {              // prefetch next chunk (overlaps MMAs)
            const int k0 = (c + 1) * 32;
            #pragma unroll
            for (int t = 0; t < 4; ++t)
                #pragma unroll
                for (int i = 0; i < 4; ++i)
                    pf[t][i] = *(const uint2*)(srcs[t] + (size_t)prow*lds[t] + k0 + pc0 + i*4);
        }

        const __nv_bfloat16* sAh = sm + 0*TILE_ELEMS;
        const __nv_bfloat16* sAl = sm + 1*TILE_ELEMS;
        const __nv_bfloat16* sBh = sm + 2*TILE_ELEMS;
        const __nv_bfloat16* sBl = sm + 3*TILE_ELEMS;

        #pragma unroll
        for (int k16 = 0; k16 < 32; k16 += 16) {
            uint32_t ah[2][4], al[2][4];
            #pragma unroll
            for (int mt = 0; mt < 2; ++mt) {
                const int m0 = wm*32 + mt*16;
                ah[mt][0] = *(const uint32_t*)(sAh + (m0+gr  )*SK + k16 + kp);
                ah[mt][1] = *(const uint32_t*)(sAh + (m0+gr+8)*SK + k16 + kp);
                ah[mt][2] = *(const uint32_t*)(sAh + (m0+gr  )*SK + k16 + kp + 8);
                ah[mt][3] = *(const uint32_t*)(sAh + (m0+gr+8)*SK + k16 + kp + 8);
                al[mt][0] = *(const uint32_t*)(sAl + (m0+gr  )*SK + k16 + kp);
                al[mt][1] = *(const uint32_t*)(sAl + (m0+gr+8)*SK + k16 + kp);
                al[mt][2] = *(const uint32_t*)(sAl + (m0+gr  )*SK + k16 + kp + 8);
                al[mt][3] = *(const uint32_t*)(sAl + (m0+gr+8)*SK + k16 + kp + 8);
            }
            #pragma unroll
            for (int nt = 0; nt < 8; ++nt) {
                const int n0 = wn*64 + nt*8;
                uint32_t bh[2], bl[2];
                bh[0] = *(const uint32_t*)(sBh + (n0+gr)*SK + k16 + kp);
                bh[1] = *(const uint32_t*)(sBh + (n0+gr)*SK + k16 + kp + 8);
                bl[0] = *(const uint32_t*)(sBl + (n0+gr)*SK + k16 + kp);
                bl[1] = *(const uint32_t*)(sBl + (n0+gr)*SK + k16 + kp + 8);
                #pragma unroll
                for (int mt = 0; mt < 2; ++mt) {
                    float* cc = &acc[(mt*8 + nt)*4];
                    mma16816(cc, ah[mt], bh);
                    mma16816(cc, ah[mt], bl);
                    mma16816(cc, al[mt], bh);
                }
            }
        }
    }

    // epilogue: acc -> global (fp32+bias, or bf16 hi/lo+bias)
    #pragma unroll
    for (int mt = 0; mt < 2; ++mt) {
        const int r0 = row0 + wm*32 + mt*16 + gr;
        #pragma unroll
        for (int nt = 0; nt < 8; ++nt) {
            const int col = col0 + wn*64 + nt*8 + kp;
            const float* cc = &acc[(mt*8 + nt)*4];
            float b0 = bias ? bias[col]     : 0.f;
            float b1 = bias ? bias[col + 1] : 0.f;
            const float v00 = cc[0] + b0, v01 = cc[1] + b1;   // row r0
            const float v10 = cc[2] + b0, v11 = cc[3] + b1;   // row r0+8
            if (outF) {
                *(float2*)(outF + (size_t)r0*ldo + col)     = make_float2(v00, v01);
                *(float2*)(outF + (size_t)(r0+8)*ldo + col) = make_float2(v10, v11);
            } else {
                __nv_bfloat16 h00 = __float2bfloat16_rn(v00), h01 = __float2bfloat16_rn(v01);
                __nv_bfloat16 h10 = __float2bfloat16_rn(v10), h11 = __float2bfloat16_rn(v11);
                __nv_bfloat16 l00 = __float2bfloat16_rn(v00 - __bfloat162float(h00));
                __nv_bfloat16 l01 = __float2bfloat16_rn(v01 - __bfloat162float(h01));
                __nv_bfloat16 l10 = __float2bfloat16_rn(v10 - __bfloat162float(h10));
                __nv_bfloat16 l11 = __float2bfloat16_rn(v11 - __bfloat162float(h11));
                *(uint32_t*)(outH + (size_t)r0*ldo + col) =
                    (uint32_t)__bfloat16_as_ushort(h00) | ((uint32_t)__bfloat16_as_ushort(h01) << 16);
                *(uint32_t*)(outH + (size_t)(r0+8)*ldo + col) =
                    (uint32_t)__bfloat16_as_ushort(h10) | ((uint32_t)__bfloat16_as_ushort(h11) << 16);
                *(uint32_t*)(outL + (size_t)r0*ldo + col) =
                    (uint32_t)__bfloat16_as_ushort(l00) | ((uint32_t)__bfloat16_as_ushort(l01) << 16);
                *(uint32_t*)(outL + (size_t)(r0+8)*ldo + col) =
                    (uint32_t)__bfloat16_as_ushort(l10) | ((uint32_t)__bfloat16_as_ushort(l11) << 16);
            }
        }
    }
}

// ---------------------------------------------------------------------------
// GEMM wrapper kernels
// ---------------------------------------------------------------------------
__global__ __launch_bounds__(256)
void spart_tc()
{
    const int t = blockIdx.x, b = blockIdx.y, s = blockIdx.z;
    const size_t tb = (size_t)b*Cc*Nn + (size_t)s*(Nn/SPL);
    tc_gemm_tile(g_cTh + tb, g_cTl + tb, Nn,
                 g_xTh + tb, g_xTl + tb, Nn,
                 Nn/SPL, (t >> 2)*128, (t & 3)*128,
                 nullptr,
                 g_Gpart + ((size_t)s*Bb + b)*Cc*Cc, nullptr, nullptr, Cc);
}

__global__ __launch_bounds__(256)
void vproj_tc(const float* __restrict__ bv)
{
    tc_gemm_tile(g_ch, g_cl, Cc, g_Wvh, g_Wvl, Cc, Cc,
                 blockIdx.x*128, blockIdx.y*128,
                 bv, nullptr, g_Vh, g_Vl, Cc);
}

__global__ __launch_bounds__(256)
void T_tc()
{
    const int b = blockIdx.z;
    tc_gemm_tile(g_Wqh, g_Wql, Cc,
                 g_Gth + (size_t)b*Cc*Cc, g_Gtl + (size_t)b*Cc*Cc, Cc,
                 Cc, blockIdx.x*128, blockIdx.y*128,
                 nullptr, g_T + (size_t)b*Cc*Cc, nullptr, nullptr, Cc);
}

__global__ __launch_bounds__(256)
void out_tc(const float* __restrict__ proj_b, float* __restrict__ out)
{
    const int row0 = blockIdx.x*128;
    const int b = row0 >> 13;
    tc_gemm_tile(g_Vh, g_Vl, Cc,
                 g_Mh + (size_t)b*Cc*Cc, g_Ml + (size_t)b*Cc*Cc, Cc,
                 Cc, row0, blockIdx.y*128,
                 proj_b, out, nullptr, nullptr, Cc);
}

// ---------------------------------------------------------------------------
// Conversion kernels
// ---------------------------------------------------------------------------
__device__ __forceinline__ void split_store4(float4 v, __nv_bfloat16* dh,
                                             __nv_bfloat16* dl, size_t i)
{
    float vv[4];
    vv[0] = v.x; vv[1] = v.y; vv[2] = v.z; vv[3] = v.w;
    uint32_t hp[2], lp[2];
    #pragma unroll
    for (int p = 0; p < 2; ++p) {
        __nv_bfloat16 h0 = __float2bfloat16_rn(vv[2*p]);
        __nv_bfloat16 h1 = __float2bfloat16_rn(vv[2*p+1]);
        __nv_bfloat16 l0 = __float2bfloat16_rn(vv[2*p]   - __bfloat162float(h0));
        __nv_bfloat16 l1 = __float2bfloat16_rn(vv[2*p+1] - __bfloat162float(h1));
        hp[p] = (uint32_t)__bfloat16_as_ushort(h0) | ((uint32_t)__bfloat16_as_ushort(h1) << 16);
        lp[p] = (uint32_t)__bfloat16_as_ushort(l0) | ((uint32_t)__bfloat16_as_ushort(l1) << 16);
    }
    *(uint2*)(dh + i) = make_uint2(hp[0], hp[1]);
    *(uint2*)(dl + i) = make_uint2(lp[0], lp[1]);
}

__global__ void conv_ctx_kernel(const float* __restrict__ ctx)
{
    const size_t i = ((size_t)blockIdx.x*256 + threadIdx.x)*4;
    split_store4(*(const float4*)(ctx + i), g_ch, g_cl, i);
}

__global__ void conv_w_kernel(const float* __restrict__ Wv, const float* __restrict__ Wq)
{
    const size_t i = ((size_t)blockIdx.x*256 + threadIdx.x)*4;
    if (blockIdx.y == 0) split_store4(*(const float4*)(Wv + i), g_Wvh, g_Wvl, i);
    else                 split_store4(*(const float4*)(Wq + i), g_Wqh, g_Wql, i);
}

__global__ void convT_kernel(const float* __restrict__ x, const float* __restrict__ ctx)
{
    const int z = blockIdx.z;
    const int b = z & 3;
    const float* src = (z < 4) ? x : ctx;
    __nv_bfloat16* dh = (z < 4) ? g_xTh : g_cTh;
    __nv_bfloat16* dl = (z < 4) ? g_xTl : g_cTl;
    const int n0 = blockIdx.x*32, c0 = blockIdx.y*32;
    __shared__ float t[32][33];
    const int tx = threadIdx.x & 31, ty = threadIdx.x >> 5;
    #pragma unroll
    for (int r = 0; r < 4; ++r)
        t[ty + r*8][tx] = src[((size_t)b*Nn + n0 + ty + r*8)*Cc + c0 + tx];
    __syncthreads();
    #pragma unroll
    for (int r = 0; r < 4; ++r) {
        const float v = t[tx][ty + r*8];
        __nv_bfloat16 h = __float2bfloat16_rn(v);
        __nv_bfloat16 l = __float2bfloat16_rn(v - __bfloat162float(h));
        const size_t o = ((size_t)b*Cc + c0 + ty + r*8)*Nn + n0 + tx;
        dh[o] = h; dl[o] = l;
    }
}

__global__ void sreduce_kernel()
{
    const size_t i4 = ((size_t)blockIdx.x*256 + threadIdx.x)*4;
    const size_t stride = (size_t)Bb*Cc*Cc;
    float4 a = *(const float4*)&g_Gpart[i4];
    #pragma unroll
    for (int s = 1; s < SPL; ++s) {
        float4 p = *(const float4*)&g_Gpart[s*stride + i4];
        a.x += p.x; a.y += p.y; a.z += p.z; a.w += p.w;
    }
    split_store4(a, g_Gth, g_Gtl, i4);
}

// ---------------------------------------------------------------------------
__global__ void colsum_kernel(const float* __restrict__ x, const float* __restrict__ ctx)
{
    const float* src = blockIdx.z ? ctx : x;
    float* dst = blockIdx.z ? &g_sc[0][0] : &g_sx[0][0];
    const int b = blockIdx.y;
    const int c = blockIdx.x*128 + (threadIdx.x & 127);
    const int q = threadIdx.x >> 7;
    const float* p = src + (size_t)b*Nn*Cc + (size_t)q*(Nn/4)*Cc + c;
    float s = 0.f;
    for (int n = 0; n < Nn/4; ++n) s += p[(size_t)n*Cc];
    __shared__ float sh[512];
    sh[threadIdx.x] = s;
    __syncthreads();
    if (q == 0)
        dst[b*Cc + c] = sh[threadIdx.x] + sh[threadIdx.x+128]
                      + sh[threadIdx.x+256] + sh[threadIdx.x+384];
}

// ---------------------------------------------------------------------------
// att: logits + rank-1 bias terms + softmax (fp32, from R4-passing version)
// ---------------------------------------------------------------------------
#define TSROW 68

__global__ __launch_bounds__(256)
void att_kernel(const float* __restrict__ Wq, const float* __restrict__ bq_,
                const float* __restrict__ Wk, const float* __restrict__ bk_,
                float* __restrict__ att_out)
{
    const int bh = blockIdx.x;
    const int b = bh >> 3, h = bh & 7, h64 = h * 64;

    __shared__ float Ts[64][TSROW];
    __shared__ float Wks[64][65];
    __shared__ float u[64], w[64];

    const int tid = threadIdx.x;
    const int d = tid >> 2, g = tid & 3;

    if (tid < 64) {
        const float* r = Wq + (size_t)(h64 + tid) * Cc;
        float a = 0.f;
        for (int c = 0; c < Cc; ++c) a = fmaf(r[c], g_sx[b][c], a);
        u[tid] = a;
    } else if (tid < 128) {
        const int e = tid - 64;
        const float* r = Wk + (size_t)(h64 + e) * Cc;
        float a = 0.f;
        for (int c = 0; c < Cc; ++c) a = fmaf(r[c], g_sc[b][c], a);
        w[e] = a;
    }

    float acc[16];
    #pragma unroll
    for (int j = 0; j < 16; ++j) acc[j] = 0.f;

    for (int k0 = 0; k0 < Cc; k0 += 64) {
        __syncthreads();
        for (int i = tid; i < 64*16; i += 256) {
            const int row = i >> 4, c4 = (i & 15) << 2;
            float4 tv = *(const float4*)&g_T[((size_t)b*Cc + h64 + row)*Cc + k0 + c4];
            *(float4*)&Ts[row][c4] = tv;
            float4 wv = *(const float4*)&Wk[(size_t)(h64 + row)*Cc + k0 + c4];
            Wks[c4+0][row] = wv.x; Wks[c4+1][row] = wv.y;
            Wks[c4+2][row] = wv.z; Wks[c4+3][row] = wv.w;
        }
        __syncthreads();
        #pragma unroll 16
        for (int k = 0; k < 64; ++k) {
            const float tv = Ts[d][k];
            #pragma unroll
            for (int j = 0; j < 16; ++j)
                acc[j] = fmaf(tv, Wks[k][g*16 + j], acc[j]);
        }
    }
    __syncthreads();

    const float bqd = bq_[h64 + d];
    const float ud  = u[d];
    float v[16];
    #pragma unroll
    for (int j = 0; j < 16; ++j) {
        const int e = g*16 + j;
        const float l = acc[j] + bqd * w[e] + bk_[h64 + e] * ud
                      + (float)Nn * bqd * bk_[h64 + e];
        v[j] = l * 0.125f;
    }

    float mx = v[0];
    #pragma unroll
    for (int j = 1; j < 16; ++j) mx = fmaxf(mx, v[j]);
    mx = fmaxf(mx, __shfl_xor_sync(0xffffffff, mx, 1));
    mx = fmaxf(mx, __shfl_xor_sync(0xffffffff, mx, 2));
    float sum = 0.f;
    #pragma unroll
    for (int j = 0; j < 16; ++j) { v[j] = expf(v[j] - mx); sum += v[j]; }
    sum += __shfl_xor_sync(0xffffffff, sum, 1);
    sum += __shfl_xor_sync(0xffffffff, sum, 2);
    const float inv = 1.f / sum;

    const size_t base = ((size_t)bh*64 + d)*64 + g*16;
    #pragma unroll
    for (int q = 0; q < 4; ++q) {
        float4 o;
        o.x = v[q*4+0]*inv; o.y = v[q*4+1]*inv;
        o.z = v[q*4+2]*inv; o.w = v[q*4+3]*inv;
        *(float4*)&g_att[base + q*4] = o;
        if (att_out) *(float4*)&att_out[base + q*4] = o;
    }
}

// ---------------------------------------------------------------------------
// buildM: M[b][cp][h64+e] = sum_d proj_w[cp][h64+d] att[b,h,d,e] -> bf16 hi/lo
// ---------------------------------------------------------------------------
__global__ __launch_bounds__(256)
void buildM_kernel(const float* __restrict__ proj_w)
{
    const int b   = blockIdx.x;
    const int cp0 = blockIdx.y * 64;
    __shared__ float atts[64][65];
    const int tid = threadIdx.x;

    for (int h = 0; h < Hh; ++h) {
        for (int i = tid; i < 64*64; i += 256) {
            const int d2 = i >> 6, e = i & 63;
            atts[d2][e] = g_att[(((size_t)(b*Hh + h)*64) + d2)*64 + e];
        }
        __syncthreads();
        for (int ww = tid; ww < 64*16; ww += 256) {
            const int cp = cp0 + (ww >> 4);
            const int e4 = (ww & 15) << 2;
            const float* pw = proj_w + (size_t)cp*Cc + h*64;
            float a0=0.f, a1=0.f, a2=0.f, a3=0.f;
            #pragma unroll 16
            for (int d2 = 0; d2 < 64; ++d2) {
                const float p = pw[d2];
                a0 = fmaf(p, atts[d2][e4+0], a0);
                a1 = fmaf(p, atts[d2][e4+1], a1);
                a2 = fmaf(p, atts[d2][e4+2], a2);
                a3 = fmaf(p, atts[d2][e4+3], a3);
            }
            split_store4(make_float4(a0, a1, a2, a3), g_Mh, g_Ml,
                         (((size_t)b*Cc + cp)*Cc) + h*64 + e4);
        }
        __syncthreads();
    }
}

// ---------------------------------------------------------------------------
extern "C" void kernel_launch(void* const* d_in, const int* in_sizes, int n_in,
                              void* d_out, int out_size)
{
    const float* x      = (const float*)d_in[0];
    const float* ctx    = (const float*)d_in[1];
    const float* Wq     = (const float*)d_in[2];
    const float* bq     = (const float*)d_in[3];
    const float* Wk     = (const float*)d_in[4];
    const float* bk     = (const float*)d_in[5];
    const float* Wv     = (const float*)d_in[6];
    const float* bv     = (const float*)d_in[7];
    const float* proj_w = (const float*)d_in[8];
    const float* proj_b = (const float*)d_in[9];
    float* out = (float*)d_out;

    float* att_out = (out_size >= OUT_ELEMS + ATT_ELEMS) ? (out + OUT_ELEMS) : nullptr;

    conv_ctx_kernel<<<16384, 256>>>(ctx);
    conv_w_kernel  <<<dim3(256, 2), 256>>>(Wv, Wq);
    convT_kernel   <<<dim3(Nn/32, Cc/32, 8), 256>>>(x, ctx);
    colsum_kernel  <<<dim3(Cc/128, Bb, 2), 512>>>(x, ctx);

    spart_tc <<<dim3(16, Bb, SPL), 256>>>();
    sreduce_kernel<<<1024, 256>>>();
    vproj_tc <<<dim3(Bb*Nn/128, Cc/128), 256>>>(bv);
    T_tc     <<<dim3(Cc/128, Cc/128, Bb), 256>>>();
    att_kernel<<<Bb*Hh, 256>>>(Wq, bq, Wk, bk, att_out);
    buildM_kernel<<<dim3(Bb, Cc/64), 256>>>(proj_w);
    out_tc   <<<dim3(Bb*Nn/128, Cc/128), 256>>>(proj_b, out);
}

// round 10
// speedup vs baseline: 1.2352x; 1.0178x over previous
#include <cuda_runtime.h>
#include <cuda_bf16.h>
#include <cstdint>
#include <math.h>

// Problem constants
#define Bb 4
#define Nn 8192
#define Cc 512
#define Hh 8
#define Dd 64
#define SPL 4                          // split-K for G over N
#define OUT_ELEMS (Bb*Nn*Cc)           // 16777216
#define ATT_ELEMS (Bb*Hh*Dd*Dd)       // 131072

// ---------------------------------------------------------------------------
// Static scratch
// ---------------------------------------------------------------------------
__device__ float g_Gpart[SPL*Bb*Cc*Cc];     // 16 MB  split-K partials of Gt
__device__ float g_T[Bb*Cc*Cc];             // 4 MB   T[b][d'][c2] fp32
__device__ float g_att[ATT_ELEMS];
__device__ float g_sx[Bb][Cc];
__device__ float g_sc[Bb][Cc];
__device__ float g_cspart[2][8][Bb][Cc];    // colsum split partials

__device__ __nv_bfloat16 g_ch[Bb*Nn*Cc],  g_cl[Bb*Nn*Cc];    // ctx (K=c major)
__device__ __nv_bfloat16 g_xTh[Bb*Cc*Nn], g_xTl[Bb*Cc*Nn];   // x^T  (K=n major)
__device__ __nv_bfloat16 g_cTh[Bb*Cc*Nn], g_cTl[Bb*Cc*Nn];   // ctx^T
__device__ __nv_bfloat16 g_Vh[Bb*Nn*Cc],  g_Vl[Bb*Nn*Cc];    // V projection
__device__ __nv_bfloat16 g_Gth[Bb*Cc*Cc], g_Gtl[Bb*Cc*Cc];   // Gt[c2][c1]
__device__ __nv_bfloat16 g_Mh[Bb*Cc*Cc],  g_Ml[Bb*Cc*Cc];    // fused M
__device__ __nv_bfloat16 g_Wvh[Cc*Cc], g_Wvl[Cc*Cc];
__device__ __nv_bfloat16 g_Wqh[Cc*Cc], g_Wql[Cc*Cc];

// ---------------------------------------------------------------------------
// mma.sync m16n8k16 bf16 + ldmatrix (sm_80+/sm_75+; supported on sm_100)
// ---------------------------------------------------------------------------
__device__ __forceinline__ void mma16816(float* c, const uint32_t* a, const uint32_t* b)
{
    asm volatile(
        "mma.sync.aligned.m16n8k16.row.col.f32.bf16.bf16.f32 "
        "{%0,%1,%2,%3}, {%4,%5,%6,%7}, {%8,%9}, {%0,%1,%2,%3};"
        : "+f"(c[0]), "+f"(c[1]), "+f"(c[2]), "+f"(c[3])
        : "r"(a[0]), "r"(a[1]), "r"(a[2]), "r"(a[3]), "r"(b[0]), "r"(b[1]));
}

__device__ __forceinline__ void ldsm_x4(uint32_t* r, const __nv_bfloat16* p)
{
    uint32_t addr = (uint32_t)__cvta_generic_to_shared(p);
    asm volatile("ldmatrix.sync.aligned.m8n8.x4.shared.b16 {%0,%1,%2,%3}, [%4];"
                 : "=r"(r[0]), "=r"(r[1]), "=r"(r[2]), "=r"(r[3]) : "r"(addr));
}

// ---------------------------------------------------------------------------
// GEMM tile: D[128x128] = sum_k A[128,K] B[128,K]^T, split-3 bf16 hi/lo.
// 256 threads (8 warps, warp tile 32x64), Kc=32, single 40KB static smem,
// register prefetch of next chunk, ldmatrix fragment loads.
// ---------------------------------------------------------------------------
#define SK 40
#define TILE_ELEMS (128*SK)                 // 5120 bf16 per tile

__device__ void tc_gemm_tile(
    const __nv_bfloat16* __restrict__ Ah, const __nv_bfloat16* __restrict__ Al, int lda,
    const __nv_bfloat16* __restrict__ Bh, const __nv_bfloat16* __restrict__ Bl, int ldb,
    int K, int row0, int col0,
    const float* __restrict__ bias,
    float* __restrict__ outF,
    __nv_bfloat16* __restrict__ outH, __nv_bfloat16* __restrict__ outL,
    int ldo)
{
    __shared__ __nv_bfloat16 sm[4*TILE_ELEMS];   // 40960 B static

    const int tid  = threadIdx.x;
    const int lane = tid & 31;
    const int wid  = tid >> 5;
    const int wm   = wid >> 1;          // 0..3  (m block of 32)
    const int wn   = wid & 1;           // 0..1  (n block of 64)
    const int gr   = lane >> 2;         // 0..7
    const int kp   = (lane & 3) << 1;   // 0,2,4,6
    const int lrow = lane & 15;         // ldmatrix row within 16
    const int lkof = (lane >> 4) * 8;   // ldmatrix k offset (0 or 8)

    const __nv_bfloat16* srcs[4];
    srcs[0] = Ah + (size_t)row0 * lda;
    srcs[1] = Al + (size_t)row0 * lda;
    srcs[2] = Bh + (size_t)col0 * ldb;
    srcs[3] = Bl + (size_t)col0 * ldb;
    const int lds[4] = {lda, lda, ldb, ldb};

    const int prow = tid >> 1;                 // 0..127
    const int pc0  = (tid & 1) * 16;

    float acc[64];
    #pragma unroll
    for (int i = 0; i < 64; ++i) acc[i] = 0.f;

    // prefetch chunk 0 into registers
    uint2 pf[4][4];
    #pragma unroll
    for (int t = 0; t < 4; ++t)
        #pragma unroll
        for (int i = 0; i < 4; ++i)
            pf[t][i] = *(const uint2*)(srcs[t] + (size_t)prow*lds[t] + pc0 + i*4);

    const int nch = K / 32;
    for (int c = 0; c < nch; ++c) {
        __syncthreads();                // smem free (previous compute done)
        #pragma unroll
        for (int t = 0; t < 4; ++t)
            #pragma unroll
            for (int i = 0; i < 4; ++i)
                *(uint2*)(sm + t*TILE_ELEMS + prow*SK + pc0 + i*4) = pf[t][i];
        __syncthreads();

        if (c + 1 < nch) {              // prefetch next chunk (overlaps MMAs)
            const int k0 = (c + 1) * 32;
            #pragma unroll
            for (int t = 0; t < 4; ++t)
                #pragma unroll
                for (int i = 0; i < 4; ++i)
                    pf[t][i] = *(const uint2*)(srcs[t] + (size_t)prow*lds[t] + k0 + pc0 + i*4);
        }

        const __nv_bfloat16* sAh = sm + 0*TILE_ELEMS;
        const __nv_bfloat16* sAl = sm + 1*TILE_ELEMS;
        const __nv_bfloat16* sBh = sm + 2*TILE_ELEMS;
        const __nv_bfloat16* sBl = sm + 3*TILE_ELEMS;

        #pragma unroll
        for (int k16 = 0; k16 < 32; k16 += 16) {
            // A fragments via ldmatrix.x4: r0..r3 = a0..a3 (16x16 tile)
            uint32_t ah[2][4], al[2][4];
            #pragma unroll
            for (int mt = 0; mt < 2; ++mt) {
                const int m0 = wm*32 + mt*16;
                ldsm_x4(ah[mt], sAh + (m0 + lrow)*SK + k16 + lkof);
                ldsm_x4(al[mt], sAl + (m0 + lrow)*SK + k16 + lkof);
            }
            // B fragments via ldmatrix.x4 per nt-pair:
            // r0 = b0(nt even), r1 = b0(nt odd), r2 = b1(even), r3 = b1(odd)
            #pragma unroll
            for (int nt2 = 0; nt2 < 4; ++nt2) {
                const int n0 = wn*64 + nt2*16;
                uint32_t bh4[4], bl4[4];
                ldsm_x4(bh4, sBh + (n0 + lrow)*SK + k16 + lkof);
                ldsm_x4(bl4, sBl + (n0 + lrow)*SK + k16 + lkof);
                uint32_t bhE[2] = {bh4[0], bh4[2]}, bhO[2] = {bh4[1], bh4[3]};
                uint32_t blE[2] = {bl4[0], bl4[2]}, blO[2] = {bl4[1], bl4[3]};
                #pragma unroll
                for (int mt = 0; mt < 2; ++mt) {
                    float* ccE = &acc[(mt*8 + 2*nt2    )*4];
                    float* ccO = &acc[(mt*8 + 2*nt2 + 1)*4];
                    mma16816(ccE, ah[mt], bhE);
                    mma16816(ccE, ah[mt], blE);
                    mma16816(ccE, al[mt], bhE);
                    mma16816(ccO, ah[mt], bhO);
                    mma16816(ccO, ah[mt], blO);
                    mma16816(ccO, al[mt], bhO);
                }
            }
        }
    }

    // epilogue: acc -> global (fp32+bias, or bf16 hi/lo+bias)
    #pragma unroll
    for (int mt = 0; mt < 2; ++mt) {
        const int r0 = row0 + wm*32 + mt*16 + gr;
        #pragma unroll
        for (int nt = 0; nt < 8; ++nt) {
            const int col = col0 + wn*64 + nt*8 + kp;
            const float* cc = &acc[(mt*8 + nt)*4];
            float b0 = bias ? bias[col]     : 0.f;
            float b1 = bias ? bias[col + 1] : 0.f;
            const float v00 = cc[0] + b0, v01 = cc[1] + b1;   // row r0
            const float v10 = cc[2] + b0, v11 = cc[3] + b1;   // row r0+8
            if (outF) {
                *(float2*)(outF + (size_t)r0*ldo + col)     = make_float2(v00, v01);
                *(float2*)(outF + (size_t)(r0+8)*ldo + col) = make_float2(v10, v11);
            } else {
                __nv_bfloat16 h00 = __float2bfloat16_rn(v00), h01 = __float2bfloat16_rn(v01);
                __nv_bfloat16 h10 = __float2bfloat16_rn(v10), h11 = __float2bfloat16_rn(v11);
                __nv_bfloat16 l00 = __float2bfloat16_rn(v00 - __bfloat162float(h00));
                __nv_bfloat16 l01 = __float2bfloat16_rn(v01 - __bfloat162float(h01));
                __nv_bfloat16 l10 = __float2bfloat16_rn(v10 - __bfloat162float(h10));
                __nv_bfloat16 l11 = __float2bfloat16_rn(v11 - __bfloat162float(h11));
                *(uint32_t*)(outH + (size_t)r0*ldo + col) =
                    (uint32_t)__bfloat16_as_ushort(h00) | ((uint32_t)__bfloat16_as_ushort(h01) << 16);
                *(uint32_t*)(outH + (size_t)(r0+8)*ldo + col) =
                    (uint32_t)__bfloat16_as_ushort(h10) | ((uint32_t)__bfloat16_as_ushort(h11) << 16);
                *(uint32_t*)(outL + (size_t)r0*ldo + col) =
                    (uint32_t)__bfloat16_as_ushort(l00) | ((uint32_t)__bfloat16_as_ushort(l01) << 16);
                *(uint32_t*)(outL + (size_t)(r0+8)*ldo + col) =
                    (uint32_t)__bfloat16_as_ushort(l10) | ((uint32_t)__bfloat16_as_ushort(l11) << 16);
            }
        }
    }
}

// ---------------------------------------------------------------------------
// GEMM wrapper kernels
// ---------------------------------------------------------------------------
__global__ __launch_bounds__(256)
void spart_tc()
{
    const int t = blockIdx.x, b = blockIdx.y, s = blockIdx.z;
    const size_t tb = (size_t)b*Cc*Nn + (size_t)s*(Nn/SPL);
    tc_gemm_tile(g_cTh + tb, g_cTl + tb, Nn,
                 g_xTh + tb, g_xTl + tb, Nn,
                 Nn/SPL, (t >> 2)*128, (t & 3)*128,
                 nullptr,
                 g_Gpart + ((size_t)s*Bb + b)*Cc*Cc, nullptr, nullptr, Cc);
}

__global__ __launch_bounds__(256)
void vproj_tc(const float* __restrict__ bv)
{
    tc_gemm_tile(g_ch, g_cl, Cc, g_Wvh, g_Wvl, Cc, Cc,
                 blockIdx.x*128, blockIdx.y*128,
                 bv, nullptr, g_Vh, g_Vl, Cc);
}

__global__ __launch_bounds__(256)
void T_tc()
{
    const int b = blockIdx.z;
    tc_gemm_tile(g_Wqh, g_Wql, Cc,
                 g_Gth + (size_t)b*Cc*Cc, g_Gtl + (size_t)b*Cc*Cc, Cc,
                 Cc, blockIdx.x*128, blockIdx.y*128,
                 nullptr, g_T + (size_t)b*Cc*Cc, nullptr, nullptr, Cc);
}

__global__ __launch_bounds__(256)
void out_tc(const float* __restrict__ proj_b, float* __restrict__ out)
{
    const int row0 = blockIdx.x*128;
    const int b = row0 >> 13;
    tc_gemm_tile(g_Vh, g_Vl, Cc,
                 g_Mh + (size_t)b*Cc*Cc, g_Ml + (size_t)b*Cc*Cc, Cc,
                 Cc, row0, blockIdx.y*128,
                 proj_b, out, nullptr, nullptr, Cc);
}

// ---------------------------------------------------------------------------
// Conversion kernels
// ---------------------------------------------------------------------------
__device__ __forceinline__ void split_store4(float4 v, __nv_bfloat16* dh,
                                             __nv_bfloat16* dl, size_t i)
{
    float vv[4];
    vv[0] = v.x; vv[1] = v.y; vv[2] = v.z; vv[3] = v.w;
    uint32_t hp[2], lp[2];
    #pragma unroll
    for (int p = 0; p < 2; ++p) {
        __nv_bfloat16 h0 = __float2bfloat16_rn(vv[2*p]);
        __nv_bfloat16 h1 = __float2bfloat16_rn(vv[2*p+1]);
        __nv_bfloat16 l0 = __float2bfloat16_rn(vv[2*p]   - __bfloat162float(h0));
        __nv_bfloat16 l1 = __float2bfloat16_rn(vv[2*p+1] - __bfloat162float(h1));
        hp[p] = (uint32_t)__bfloat16_as_ushort(h0) | ((uint32_t)__bfloat16_as_ushort(h1) << 16);
        lp[p] = (uint32_t)__bfloat16_as_ushort(l0) | ((uint32_t)__bfloat16_as_ushort(l1) << 16);
    }
    *(uint2*)(dh + i) = make_uint2(hp[0], hp[1]);
    *(uint2*)(dl + i) = make_uint2(lp[0], lp[1]);
}

__global__ void conv_ctx_kernel(const float* __restrict__ ctx)
{
    const size_t i = ((size_t)blockIdx.x*256 + threadIdx.x)*4;
    split_store4(*(const float4*)(ctx + i), g_ch, g_cl, i);
}

__global__ void conv_w_kernel(const float* __restrict__ Wv, const float* __restrict__ Wq)
{
    const size_t i = ((size_t)blockIdx.x*256 + threadIdx.x)*4;
    if (blockIdx.y == 0) split_store4(*(const float4*)(Wv + i), g_Wvh, g_Wvl, i);
    else                 split_store4(*(const float4*)(Wq + i), g_Wqh, g_Wql, i);
}

__global__ void convT_kernel(const float* __restrict__ x, const float* __restrict__ ctx)
{
    const int z = blockIdx.z;
    const int b = z & 3;
    const float* src = (z < 4) ? x : ctx;
    __nv_bfloat16* dh = (z < 4) ? g_xTh : g_cTh;
    __nv_bfloat16* dl = (z < 4) ? g_xTl : g_cTl;
    const int n0 = blockIdx.x*32, c0 = blockIdx.y*32;
    __shared__ float t[32][33];
    const int tx = threadIdx.x & 31, ty = threadIdx.x >> 5;
    #pragma unroll
    for (int r = 0; r < 4; ++r)
        t[ty + r*8][tx] = src[((size_t)b*Nn + n0 + ty + r*8)*Cc + c0 + tx];
    __syncthreads();
    #pragma unroll
    for (int r = 0; r < 4; ++r) {
        const float v = t[tx][ty + r*8];
        __nv_bfloat16 h = __float2bfloat16_rn(v);
        __nv_bfloat16 l = __float2bfloat16_rn(v - __bfloat162float(h));
        const size_t o = ((size_t)b*Cc + c0 + ty + r*8)*Nn + n0 + tx;
        dh[o] = h; dl[o] = l;
    }
}

__global__ void sreduce_kernel()
{
    const size_t i4 = ((size_t)blockIdx.x*256 + threadIdx.x)*4;
    const size_t stride = (size_t)Bb*Cc*Cc;
    float4 a = *(const float4*)&g_Gpart[i4];
    #pragma unroll
    for (int s = 1; s < SPL; ++s) {
        float4 p = *(const float4*)&g_Gpart[s*stride + i4];
        a.x += p.x; a.y += p.y; a.z += p.z; a.w += p.w;
    }
    split_store4(a, g_Gth, g_Gtl, i4);
}

// ---------------------------------------------------------------------------
// colsum split over n: 256 CTAs of partials + tiny reduce (was 32-CTA, 20% BW)
// ---------------------------------------------------------------------------
__global__ void colsum_part_kernel(const float* __restrict__ x, const float* __restrict__ ctx)
{
    const int z = blockIdx.z;
    const int sid = z >> 3, chunk = z & 7;
    const float* src = sid ? ctx : x;
    const int b = blockIdx.y;
    const int c = blockIdx.x*128 + threadIdx.x;
    const float* p = src + (size_t)b*Nn*Cc + (size_t)chunk*(Nn/8)*Cc + c;
    float s = 0.f;
    #pragma unroll 8
    for (int n = 0; n < Nn/8; ++n) s += p[(size_t)n*Cc];
    g_cspart[sid][chunk][b][c] = s;
}

__global__ void colsum_red_kernel()
{
    const int sid = blockIdx.z;
    const int b = blockIdx.y;
    const int c = blockIdx.x*128 + threadIdx.x;
    float s = 0.f;
    #pragma unroll
    for (int k = 0; k < 8; ++k) s += g_cspart[sid][k][b][c];
    if (sid) g_sc[b][c] = s; else g_sx[b][c] = s;
}

// ---------------------------------------------------------------------------
// att: logits + rank-1 bias terms + softmax (fp32, from R4-passing version)
// ---------------------------------------------------------------------------
#define TSROW 68

__global__ __launch_bounds__(256)
void att_kernel(const float* __restrict__ Wq, const float* __restrict__ bq_,
                const float* __restrict__ Wk, const float* __restrict__ bk_,
                float* __restrict__ att_out)
{
    const int bh = blockIdx.x;
    const int b = bh >> 3, h = bh & 7, h64 = h * 64;

    __shared__ float Ts[64][TSROW];
    __shared__ float Wks[64][65];
    __shared__ float u[64], w[64];

    const int tid = threadIdx.x;
    const int d = tid >> 2, g = tid & 3;

    if (tid < 64) {
        const float* r = Wq + (size_t)(h64 + tid) * Cc;
        float a = 0.f;
        for (int c = 0; c < Cc; ++c) a = fmaf(r[c], g_sx[b][c], a);
        u[tid] = a;
    } else if (tid < 128) {
        const int e = tid - 64;
        const float* r = Wk + (size_t)(h64 + e) * Cc;
        float a = 0.f;
        for (int c = 0; c < Cc; ++c) a = fmaf(r[c], g_sc[b][c], a);
        w[e] = a;
    }

    float acc[16];
    #pragma unroll
    for (int j = 0; j < 16; ++j) acc[j] = 0.f;

    for (int k0 = 0; k0 < Cc; k0 += 64) {
        __syncthreads();
        for (int i = tid; i < 64*16; i += 256) {
            const int row = i >> 4, c4 = (i & 15) << 2;
            float4 tv = *(const float4*)&g_T[((size_t)b*Cc + h64 + row)*Cc + k0 + c4];
            *(float4*)&Ts[row][c4] = tv;
            float4 wv = *(const float4*)&Wk[(size_t)(h64 + row)*Cc + k0 + c4];
            Wks[c4+0][row] = wv.x; Wks[c4+1][row] = wv.y;
            Wks[c4+2][row] = wv.z; Wks[c4+3][row] = wv.w;
        }
        __syncthreads();
        #pragma unroll 16
        for (int k = 0; k < 64; ++k) {
            const float tv = Ts[d][k];
            #pragma unroll
            for (int j = 0; j < 16; ++j)
                acc[j] = fmaf(tv, Wks[k][g*16 + j], acc[j]);
        }
    }
    __syncthreads();

    const float bqd = bq_[h64 + d];
    const float ud  = u[d];
    float v[16];
    #pragma unroll
    for (int j = 0; j < 16; ++j) {
        const int e = g*16 + j;
        const float l = acc[j] + bqd * w[e] + bk_[h64 + e] * ud
                      + (float)Nn * bqd * bk_[h64 + e];
        v[j] = l * 0.125f;
    }

    float mx = v[0];
    #pragma unroll
    for (int j = 1; j < 16; ++j) mx = fmaxf(mx, v[j]);
    mx = fmaxf(mx, __shfl_xor_sync(0xffffffff, mx, 1));
    mx = fmaxf(mx, __shfl_xor_sync(0xffffffff, mx, 2));
    float sum = 0.f;
    #pragma unroll
    for (int j = 0; j < 16; ++j) { v[j] = expf(v[j] - mx); sum += v[j]; }
    sum += __shfl_xor_sync(0xffffffff, sum, 1);
    sum += __shfl_xor_sync(0xffffffff, sum, 2);
    const float inv = 1.f / sum;

    const size_t base = ((size_t)bh*64 + d)*64 + g*16;
    #pragma unroll
    for (int q = 0; q < 4; ++q) {
        float4 o;
        o.x = v[q*4+0]*inv; o.y = v[q*4+1]*inv;
        o.z = v[q*4+2]*inv; o.w = v[q*4+3]*inv;
        *(float4*)&g_att[base + q*4] = o;
        if (att_out) *(float4*)&att_out[base + q*4] = o;
    }
}

// ---------------------------------------------------------------------------
// buildM: M[b][cp][h64+e] = sum_d proj_w[cp][h64+d] att[b,h,d,e] -> bf16 hi/lo
// ---------------------------------------------------------------------------
__global__ __launch_bounds__(256)
void buildM_kernel(const float* __restrict__ proj_w)
{
    const int b   = blockIdx.x;
    const int cp0 = blockIdx.y * 64;
    __shared__ float atts[64][65];
    const int tid = threadIdx.x;

    for (int h = 0; h < Hh; ++h) {
        for (int i = tid; i < 64*64; i += 256) {
            const int d2 = i >> 6, e = i & 63;
            atts[d2][e] = g_att[(((size_t)(b*Hh + h)*64) + d2)*64 + e];
        }
        __syncthreads();
        for (int ww = tid; ww < 64*16; ww += 256) {
            const int cp = cp0 + (ww >> 4);
            const int e4 = (ww & 15) << 2;
            const float* pw = proj_w + (size_t)cp*Cc + h*64;
            float a0=0.f, a1=0.f, a2=0.f, a3=0.f;
            #pragma unroll 16
            for (int d2 = 0; d2 < 64; ++d2) {
                const float p = pw[d2];
                a0 = fmaf(p, atts[d2][e4+0], a0);
                a1 = fmaf(p, atts[d2][e4+1], a1);
                a2 = fmaf(p, atts[d2][e4+2], a2);
                a3 = fmaf(p, atts[d2][e4+3], a3);
            }
            split_store4(make_float4(a0, a1, a2, a3), g_Mh, g_Ml,
                         (((size_t)b*Cc + cp)*Cc) + h*64 + e4);
        }
        __syncthreads();
    }
}

// ---------------------------------------------------------------------------
extern "C" void kernel_launch(void* const* d_in, const int* in_sizes, int n_in,
                              void* d_out, int out_size)
{
    const float* x      = (const float*)d_in[0];
    const float* ctx    = (const float*)d_in[1];
    const float* Wq     = (const float*)d_in[2];
    const float* bq     = (const float*)d_in[3];
    const float* Wk     = (const float*)d_in[4];
    const float* bk     = (const float*)d_in[5];
    const float* Wv     = (const float*)d_in[6];
    const float* bv     = (const float*)d_in[7];
    const float* proj_w = (const float*)d_in[8];
    const float* proj_b = (const float*)d_in[9];
    float* out = (float*)d_out;

    float* att_out = (out_size >= OUT_ELEMS + ATT_ELEMS) ? (out + OUT_ELEMS) : nullptr;

    conv_ctx_kernel <<<16384, 256>>>(ctx);
    conv_w_kernel   <<<dim3(256, 2), 256>>>(Wv, Wq);
    convT_kernel    <<<dim3(Nn/32, Cc/32, 8), 256>>>(x, ctx);
    colsum_part_kernel<<<dim3(Cc/128, Bb, 16), 128>>>(x, ctx);
    colsum_red_kernel <<<dim3(Cc/128, Bb, 2), 128>>>();

    spart_tc <<<dim3(16, Bb, SPL), 256>>>();
    sreduce_kernel<<<1024, 256>>>();
    vproj_tc <<<dim3(Bb*Nn/128, Cc/128), 256>>>(bv);
    T_tc     <<<dim3(Cc/128, Cc/128, Bb), 256>>>();
    att_kernel<<<Bb*Hh, 256>>>(Wq, bq, Wk, bk, att_out);
    buildM_kernel<<<dim3(Bb, Cc/64), 256>>>(proj_w);
    out_tc   <<<dim3(Bb*Nn/128, Cc/128), 256>>>(proj_b, out);
}